// round 2
// baseline (speedup 1.0000x reference)
#include <cuda_runtime.h>
#include <math.h>

#define NF 5
#define D 64
#define NHID 128
#define H 8192     /* D*NHID */
#define BATCH 4096
#define BM 32
#define NTH 256

// Precomputed normalized weights (input-dependent but batch-independent)
__device__ float g_wn1T[NF * D * H];          // [f][j][r]   (10 MB)
__device__ float g_wn2T[NF * D * NHID * D];   // [f][i][k][oc] (10 MB, zeros folded)
__device__ float g_c[NF * D * NHID];          // [f][i][k] = wpl1_diag + wpl2_diag

__device__ __forceinline__ float softplusf(float z) {
    return fmaxf(z, 0.f) + log1pf(expf(-fabsf(z)));
}

// ---------------------------------------------------------------------------
// prep1: per row r of W1 (8192 rows x 64 cols per flow), block i = r>>7.
// w[j] = W1[r,j] (j<i), exp(W1[r,i]) (j==i), 0 (j>i). Row-normalize, scale by
// exp(d1). Store transposed [j][r] for coalesced staging. Also c = wpl1 diag.
// ---------------------------------------------------------------------------
__global__ void prep1(const float* __restrict__ W1, const float* __restrict__ d1) {
    int idx = blockIdx.x * blockDim.x + threadIdx.x;
    if (idx >= NF * H) return;
    int f = idx / H, r = idx % H;
    int i = r >> 7, k = r & 127;
    const float* Wrow = W1 + (size_t)(f * H + r) * D;
    float dv = d1[f * H + r];
    float wdiag = expf(Wrow[i]);
    float wsn = wdiag * wdiag;
    for (int j = 0; j < i; j++) { float wv = Wrow[j]; wsn += wv * wv; }
    float scale = expf(dv) * rsqrtf(wsn);
    float* dst = g_wn1T + (size_t)f * D * H + r;
    for (int j = 0; j < D; j++) {
        float wv = (j < i) ? Wrow[j] : ((j == i) ? wdiag : 0.f);
        dst[(size_t)j * H] = wv * scale;
    }
    g_c[(f * D + i) * NHID + k] = dv + Wrow[i] - 0.5f * logf(wsn);
}

// ---------------------------------------------------------------------------
// prep2: one CTA per (flow, output col oc). Row oc of W2 has 8192 cols;
// block jb: W2 (jb<oc), exp(W2) (jb==oc), 0 (jb>oc). Normalize, store as
// [f][i][k][oc] so the main kernel stages contiguous 128x64 tiles.
// Adds wpl2 diag into g_c (runs after prep1, same stream -> ordered).
// ---------------------------------------------------------------------------
__global__ void prep2(const float* __restrict__ W2, const float* __restrict__ d2) {
    int f = blockIdx.x >> 6;
    int oc = blockIdx.x & 63;
    int tid = threadIdx.x;
    const float* Wrow = W2 + (size_t)(f * D + oc) * H;
    __shared__ float red[128];
    float wsn = 0.f;
    int lim = (oc + 1) * NHID;
    for (int j = tid; j < lim; j += 128) {
        int jb = j >> 7;
        float wv = (jb == oc) ? expf(Wrow[j]) : Wrow[j];
        wsn += wv * wv;
    }
    red[tid] = wsn;
    __syncthreads();
    for (int s = 64; s > 0; s >>= 1) {
        if (tid < s) red[tid] += red[tid + s];
        __syncthreads();
    }
    wsn = red[0];
    float dv = d2[f * D + oc];
    float scale = expf(dv) * rsqrtf(wsn);
    float* base = g_wn2T + (size_t)f * D * NHID * D;
    for (int j = tid; j < H; j += 128) {
        int jb = j >> 7, k = j & 127;
        float wv = (jb < oc) ? Wrow[j] : ((jb == oc) ? expf(Wrow[j]) : 0.f);
        base[((size_t)jb * NHID + k) * D + oc] = wv * scale;
    }
    // wpl2 diagonal contribution into c (unique writer per element)
    {
        int k = tid;            // blockDim = 128
        g_c[(f * D + oc) * NHID + k] += dv + Wrow[oc * NHID + k] - 0.5f * logf(wsn);
    }
}

// ---------------------------------------------------------------------------
// Main fused kernel: each CTA owns BM=32 batch rows through all 5 flows.
// Per i-block: stage w1 rows 0..i (triangular) + w2 tile -> h in regs ->
// tanh + log-dtanh -> smem -> per-row logsumexp (8-lane shuffle) -> y accum.
// ---------------------------------------------------------------------------
__global__ void __launch_bounds__(NTH, 2) bnaf_main(
    const float* __restrict__ x, const float* __restrict__ b1,
    const float* __restrict__ b2, const float* __restrict__ gates,
    float* __restrict__ out)
{
    extern __shared__ float sm[];
    float* xs  = sm;                   // BM*D     = 2048
    float* w1s = xs + BM * D;          // D*NHID   = 8192
    float* w2s = w1s + D * NHID;       // NHID*D   = 8192
    float* ts  = w2s + NHID * D;       // BM*NHID  = 4096
    float* ps  = ts + BM * NHID;       // BM*NHID  = 4096
    float* lds_s = ps + BM * NHID;     // BM

    const int tid = threadIdx.x;
    const int b0 = blockIdx.x * BM;
    const float LN2 = 0.6931471805599453f;

    {   // load x tile, coalesced float4
        const float4* xg = (const float4*)(x + (size_t)b0 * D);
        float4* xs4 = (float4*)xs;
        for (int q = tid; q < BM * D / 4; q += NTH) xs4[q] = xg[q];
    }
    if (tid < BM) lds_s[tid] = 0.f;
    __syncthreads();

    const int kc = tid & 63;       // h-column (and output-column) lane
    const int rg = tid >> 6;       // row group 0..3
    const int rbase = rg * 8;      // 8 rows per thread
    const int oc = kc;

    for (int f = 0; f < NF; f++) {
        const bool gated = (f < NF - 1);
        const float gate = gated ? gates[f] : 0.f;
        const float sg = gated ? (1.f / (1.f + expf(-gate))) : 0.f;
        const float spg = gated ? softplusf(gate) : 0.f;

        float yacc[8];
        {
            float b2v = b2[f * D + oc];
            #pragma unroll
            for (int rr = 0; rr < 8; rr++) yacc[rr] = b2v;
        }

        const float* wn1f = g_wn1T + (size_t)f * D * H;
        const float* wn2f = g_wn2T + (size_t)f * D * NHID * D;

        for (int i = 0; i < D; i++) {
            // ---- stage weights (w1 only rows j<=i; rows >i are zero anyway)
            {
                const int n4 = (i + 1) * (NHID / 4);
                for (int q = tid; q < n4; q += NTH) {
                    int j = q >> 5;          // NHID/4 = 32 float4 per j
                    int c4 = q & 31;
                    float4 v = *(const float4*)(wn1f + (size_t)j * H + i * NHID + c4 * 4);
                    *(float4*)(w1s + j * NHID + c4 * 4) = v;
                }
                const float4* src = (const float4*)(wn2f + (size_t)i * NHID * D);
                float4* dst = (float4*)w2s;
                for (int q = tid; q < NHID * D / 4; q += NTH) dst[q] = src[q];
            }
            __syncthreads();

            // ---- phase 1: h[r][kc], h[r][kc+64] for 8 rows, j <= i only
            float a0[8], a1[8];
            {
                float b1a = b1[f * H + i * NHID + kc];
                float b1b = b1[f * H + i * NHID + kc + 64];
                #pragma unroll
                for (int rr = 0; rr < 8; rr++) { a0[rr] = b1a; a1[rr] = b1b; }
            }
            int j = 0;
            for (; j + 3 <= i; j += 4) {
                float w00 = w1s[(j + 0) * NHID + kc], w01 = w1s[(j + 1) * NHID + kc];
                float w02 = w1s[(j + 2) * NHID + kc], w03 = w1s[(j + 3) * NHID + kc];
                float w10 = w1s[(j + 0) * NHID + kc + 64], w11 = w1s[(j + 1) * NHID + kc + 64];
                float w12 = w1s[(j + 2) * NHID + kc + 64], w13 = w1s[(j + 3) * NHID + kc + 64];
                #pragma unroll
                for (int rr = 0; rr < 8; rr++) {
                    float4 xv = *(const float4*)(xs + (rbase + rr) * D + j);
                    a0[rr] += xv.x * w00 + xv.y * w01 + xv.z * w02 + xv.w * w03;
                    a1[rr] += xv.x * w10 + xv.y * w11 + xv.z * w12 + xv.w * w13;
                }
            }
            for (; j <= i; j++) {
                float w0 = w1s[j * NHID + kc], w1 = w1s[j * NHID + kc + 64];
                #pragma unroll
                for (int rr = 0; rr < 8; rr++) {
                    float xv = xs[(rbase + rr) * D + j];
                    a0[rr] += xv * w0;
                    a1[rr] += xv * w1;
                }
            }

            // ---- tanh + log(1 - tanh^2) (stable form), write t and p tiles
            {
                float ca = g_c[(f * D + i) * NHID + kc];
                float cb = g_c[(f * D + i) * NHID + kc + 64];
                #pragma unroll
                for (int rr = 0; rr < 8; rr++) {
                    int r = rbase + rr;
                    float h0 = a0[rr], h1 = a1[rr];
                    float t0 = tanhf(h0), t1 = tanhf(h1);
                    ts[r * NHID + kc] = t0;
                    ts[r * NHID + kc + 64] = t1;
                    float l0 = -2.f * (h0 - LN2 + softplusf(-2.f * h0));
                    float l1 = -2.f * (h1 - LN2 + softplusf(-2.f * h1));
                    ps[r * NHID + kc] = ca + l0;
                    ps[r * NHID + kc + 64] = cb + l1;
                }
            }
            __syncthreads();

            // ---- per-row logsumexp over 128 (8 lanes/row, butterfly shuffle)
            {
                int row = tid >> 3, sub = tid & 7;
                const float* pr = ps + row * NHID;
                float mx = -1e30f;
                #pragma unroll
                for (int m = 0; m < 16; m++) mx = fmaxf(mx, pr[sub + 8 * m]);
                #pragma unroll
                for (int o = 4; o > 0; o >>= 1)
                    mx = fmaxf(mx, __shfl_xor_sync(0xffffffffu, mx, o));
                float se = 0.f;
                #pragma unroll
                for (int m = 0; m < 16; m++) se += expf(pr[sub + 8 * m] - mx);
                #pragma unroll
                for (int o = 4; o > 0; o >>= 1)
                    se += __shfl_xor_sync(0xffffffffu, se, o);
                if (sub == 0) {
                    float g = mx + logf(se);
                    float term = gated ? (softplusf(g + gate) - spg) : g;
                    lds_s[row] += term;
                }
            }

            // ---- phase 2: y[r][oc] += t . wn2  (warp-uniform skip of zero cols)
            if ((oc | 31) >= i) {
                for (int k = 0; k < NHID; k += 4) {
                    float w0 = w2s[(k + 0) * D + oc], w1 = w2s[(k + 1) * D + oc];
                    float w2v = w2s[(k + 2) * D + oc], w3 = w2s[(k + 3) * D + oc];
                    #pragma unroll
                    for (int rr = 0; rr < 8; rr++) {
                        float4 tv = *(const float4*)(ts + (rbase + rr) * NHID + k);
                        yacc[rr] += tv.x * w0 + tv.y * w1 + tv.z * w2v + tv.w * w3;
                    }
                }
            }
            __syncthreads();
        }

        // ---- gate-combine and reverse (or final output)
        if (f < NF - 1) {
            float xo[8];
            #pragma unroll
            for (int rr = 0; rr < 8; rr++) {
                float xv = xs[(rbase + rr) * D + oc];
                xo[rr] = sg * yacc[rr] + (1.f - sg) * xv;
            }
            __syncthreads();
            #pragma unroll
            for (int rr = 0; rr < 8; rr++)
                xs[(rbase + rr) * D + (D - 1 - oc)] = xo[rr];
            __syncthreads();
        } else {
            #pragma unroll
            for (int rr = 0; rr < 8; rr++)
                out[(size_t)(b0 + rbase + rr) * D + oc] = yacc[rr];
        }
    }

    if (tid < BM) out[(size_t)BATCH * D + b0 + tid] = lds_s[tid];
}

static const int SMEM_BYTES = (BM * D + D * NHID + NHID * D + 2 * BM * NHID + BM) * 4;

extern "C" void kernel_launch(void* const* d_in, const int* in_sizes, int n_in,
                              void* d_out, int out_size) {
    const float* x  = (const float*)d_in[0];
    const float* W1 = (const float*)d_in[1];
    const float* d1 = (const float*)d_in[2];
    const float* b1 = (const float*)d_in[3];
    const float* W2 = (const float*)d_in[4];
    const float* d2 = (const float*)d_in[5];
    const float* b2 = (const float*)d_in[6];
    const float* gates = (const float*)d_in[7];
    float* out = (float*)d_out;

    prep1<<<(NF * H + 255) / 256, 256>>>(W1, d1);
    prep2<<<NF * D, 128>>>(W2, d2);

    cudaFuncSetAttribute(bnaf_main, cudaFuncAttributeMaxDynamicSharedMemorySize, SMEM_BYTES);
    bnaf_main<<<BATCH / BM, NTH, SMEM_BYTES>>>(x, b1, b2, gates, out);
}

// round 6
// speedup vs baseline: 1.0001x; 1.0001x over previous
#include <cuda_runtime.h>
#include <math.h>

#define NF 5
#define D 64
#define NHID 128
#define H 8192     /* D*NHID */
#define BATCH 4096
#define BM 32
#define NTH 256

// Precomputed normalized weights (input-dependent but batch-independent)
__device__ float g_wn1T[NF * D * H];          // [f][j][r]   (10 MB)
__device__ float g_wn2T[NF * D * NHID * D];   // [f][i][k][oc] (10 MB, zeros folded)
__device__ float g_c[NF * D * NHID];          // [f][i][k] = wpl1_diag + wpl2_diag

__device__ __forceinline__ float softplusf(float z) {
    return fmaxf(z, 0.f) + log1pf(expf(-fabsf(z)));
}

// ---------------------------------------------------------------------------
// prep1: per row r of W1 (8192 rows x 64 cols per flow), block i = r>>7.
// w[j] = W1[r,j] (j<i), exp(W1[r,i]) (j==i), 0 (j>i). Row-normalize, scale by
// exp(d1). Store transposed [j][r] for coalesced staging. Also c = wpl1 diag.
// ---------------------------------------------------------------------------
__global__ void prep1(const float* __restrict__ W1, const float* __restrict__ d1) {
    int idx = blockIdx.x * blockDim.x + threadIdx.x;
    if (idx >= NF * H) return;
    int f = idx / H, r = idx % H;
    int i = r >> 7, k = r & 127;
    const float* Wrow = W1 + (size_t)(f * H + r) * D;
    float dv = d1[f * H + r];
    float wdiag = expf(Wrow[i]);
    float wsn = wdiag * wdiag;
    for (int j = 0; j < i; j++) { float wv = Wrow[j]; wsn += wv * wv; }
    float scale = expf(dv) * rsqrtf(wsn);
    float* dst = g_wn1T + (size_t)f * D * H + r;
    for (int j = 0; j < D; j++) {
        float wv = (j < i) ? Wrow[j] : ((j == i) ? wdiag : 0.f);
        dst[(size_t)j * H] = wv * scale;
    }
    g_c[(f * D + i) * NHID + k] = dv + Wrow[i] - 0.5f * logf(wsn);
}

// ---------------------------------------------------------------------------
// prep2: one CTA per (flow, output col oc). Row oc of W2 has 8192 cols;
// block jb: W2 (jb<oc), exp(W2) (jb==oc), 0 (jb>oc). Normalize, store as
// [f][i][k][oc] so the main kernel stages contiguous 128x64 tiles.
// Adds wpl2 diag into g_c (runs after prep1, same stream -> ordered).
// ---------------------------------------------------------------------------
__global__ void prep2(const float* __restrict__ W2, const float* __restrict__ d2) {
    int f = blockIdx.x >> 6;
    int oc = blockIdx.x & 63;
    int tid = threadIdx.x;
    const float* Wrow = W2 + (size_t)(f * D + oc) * H;
    __shared__ float red[128];
    float wsn = 0.f;
    int lim = (oc + 1) * NHID;
    for (int j = tid; j < lim; j += 128) {
        int jb = j >> 7;
        float wv = (jb == oc) ? expf(Wrow[j]) : Wrow[j];
        wsn += wv * wv;
    }
    red[tid] = wsn;
    __syncthreads();
    for (int s = 64; s > 0; s >>= 1) {
        if (tid < s) red[tid] += red[tid + s];
        __syncthreads();
    }
    wsn = red[0];
    float dv = d2[f * D + oc];
    float scale = expf(dv) * rsqrtf(wsn);
    float* base = g_wn2T + (size_t)f * D * NHID * D;
    for (int j = tid; j < H; j += 128) {
        int jb = j >> 7, k = j & 127;
        float wv = (jb < oc) ? Wrow[j] : ((jb == oc) ? expf(Wrow[j]) : 0.f);
        base[((size_t)jb * NHID + k) * D + oc] = wv * scale;
    }
    // wpl2 diagonal contribution into c (unique writer per element)
    {
        int k = tid;            // blockDim = 128
        g_c[(f * D + oc) * NHID + k] += dv + Wrow[oc * NHID + k] - 0.5f * logf(wsn);
    }
}

// ---------------------------------------------------------------------------
// Main fused kernel: each CTA owns BM=32 batch rows through all 5 flows.
// Per i-block: stage w1 rows 0..i (triangular) + w2 tile -> h in regs ->
// tanh + log-dtanh -> smem -> per-row logsumexp (8-lane shuffle) -> y accum.
// ---------------------------------------------------------------------------
__global__ void __launch_bounds__(NTH, 2) bnaf_main(
    const float* __restrict__ x, const float* __restrict__ b1,
    const float* __restrict__ b2, const float* __restrict__ gates,
    float* __restrict__ out)
{
    extern __shared__ float sm[];
    float* xs  = sm;                   // BM*D     = 2048
    float* w1s = xs + BM * D;          // D*NHID   = 8192
    float* w2s = w1s + D * NHID;       // NHID*D   = 8192
    float* ts  = w2s + NHID * D;       // BM*NHID  = 4096
    float* ps  = ts + BM * NHID;       // BM*NHID  = 4096
    float* lds_s = ps + BM * NHID;     // BM

    const int tid = threadIdx.x;
    const int b0 = blockIdx.x * BM;
    const float LN2 = 0.6931471805599453f;

    {   // load x tile, coalesced float4
        const float4* xg = (const float4*)(x + (size_t)b0 * D);
        float4* xs4 = (float4*)xs;
        for (int q = tid; q < BM * D / 4; q += NTH) xs4[q] = xg[q];
    }
    if (tid < BM) lds_s[tid] = 0.f;
    __syncthreads();

    const int kc = tid & 63;       // h-column (and output-column) lane
    const int rg = tid >> 6;       // row group 0..3
    const int rbase = rg * 8;      // 8 rows per thread
    const int oc = kc;

    for (int f = 0; f < NF; f++) {
        const bool gated = (f < NF - 1);
        const float gate = gated ? gates[f] : 0.f;
        const float sg = gated ? (1.f / (1.f + expf(-gate))) : 0.f;
        const float spg = gated ? softplusf(gate) : 0.f;

        float yacc[8];
        {
            float b2v = b2[f * D + oc];
            #pragma unroll
            for (int rr = 0; rr < 8; rr++) yacc[rr] = b2v;
        }

        const float* wn1f = g_wn1T + (size_t)f * D * H;
        const float* wn2f = g_wn2T + (size_t)f * D * NHID * D;

        for (int i = 0; i < D; i++) {
            // ---- stage weights (w1 only rows j<=i; rows >i are zero anyway)
            {
                const int n4 = (i + 1) * (NHID / 4);
                for (int q = tid; q < n4; q += NTH) {
                    int j = q >> 5;          // NHID/4 = 32 float4 per j
                    int c4 = q & 31;
                    float4 v = *(const float4*)(wn1f + (size_t)j * H + i * NHID + c4 * 4);
                    *(float4*)(w1s + j * NHID + c4 * 4) = v;
                }
                const float4* src = (const float4*)(wn2f + (size_t)i * NHID * D);
                float4* dst = (float4*)w2s;
                for (int q = tid; q < NHID * D / 4; q += NTH) dst[q] = src[q];
            }
            __syncthreads();

            // ---- phase 1: h[r][kc], h[r][kc+64] for 8 rows, j <= i only
            float a0[8], a1[8];
            {
                float b1a = b1[f * H + i * NHID + kc];
                float b1b = b1[f * H + i * NHID + kc + 64];
                #pragma unroll
                for (int rr = 0; rr < 8; rr++) { a0[rr] = b1a; a1[rr] = b1b; }
            }
            int j = 0;
            for (; j + 3 <= i; j += 4) {
                float w00 = w1s[(j + 0) * NHID + kc], w01 = w1s[(j + 1) * NHID + kc];
                float w02 = w1s[(j + 2) * NHID + kc], w03 = w1s[(j + 3) * NHID + kc];
                float w10 = w1s[(j + 0) * NHID + kc + 64], w11 = w1s[(j + 1) * NHID + kc + 64];
                float w12 = w1s[(j + 2) * NHID + kc + 64], w13 = w1s[(j + 3) * NHID + kc + 64];
                #pragma unroll
                for (int rr = 0; rr < 8; rr++) {
                    float4 xv = *(const float4*)(xs + (rbase + rr) * D + j);
                    a0[rr] += xv.x * w00 + xv.y * w01 + xv.z * w02 + xv.w * w03;
                    a1[rr] += xv.x * w10 + xv.y * w11 + xv.z * w12 + xv.w * w13;
                }
            }
            for (; j <= i; j++) {
                float w0 = w1s[j * NHID + kc], w1 = w1s[j * NHID + kc + 64];
                #pragma unroll
                for (int rr = 0; rr < 8; rr++) {
                    float xv = xs[(rbase + rr) * D + j];
                    a0[rr] += xv * w0;
                    a1[rr] += xv * w1;
                }
            }

            // ---- tanh + log(1 - tanh^2) (stable form), write t and p tiles
            {
                float ca = g_c[(f * D + i) * NHID + kc];
                float cb = g_c[(f * D + i) * NHID + kc + 64];
                #pragma unroll
                for (int rr = 0; rr < 8; rr++) {
                    int r = rbase + rr;
                    float h0 = a0[rr], h1 = a1[rr];
                    float t0 = tanhf(h0), t1 = tanhf(h1);
                    ts[r * NHID + kc] = t0;
                    ts[r * NHID + kc + 64] = t1;
                    float l0 = -2.f * (h0 - LN2 + softplusf(-2.f * h0));
                    float l1 = -2.f * (h1 - LN2 + softplusf(-2.f * h1));
                    ps[r * NHID + kc] = ca + l0;
                    ps[r * NHID + kc + 64] = cb + l1;
                }
            }
            __syncthreads();

            // ---- per-row logsumexp over 128 (8 lanes/row, butterfly shuffle)
            {
                int row = tid >> 3, sub = tid & 7;
                const float* pr = ps + row * NHID;
                float mx = -1e30f;
                #pragma unroll
                for (int m = 0; m < 16; m++) mx = fmaxf(mx, pr[sub + 8 * m]);
                #pragma unroll
                for (int o = 4; o > 0; o >>= 1)
                    mx = fmaxf(mx, __shfl_xor_sync(0xffffffffu, mx, o));
                float se = 0.f;
                #pragma unroll
                for (int m = 0; m < 16; m++) se += expf(pr[sub + 8 * m] - mx);
                #pragma unroll
                for (int o = 4; o > 0; o >>= 1)
                    se += __shfl_xor_sync(0xffffffffu, se, o);
                if (sub == 0) {
                    float g = mx + logf(se);
                    float term = gated ? (softplusf(g + gate) - spg) : g;
                    lds_s[row] += term;
                }
            }

            // ---- phase 2: y[r][oc] += t . wn2  (warp-uniform skip of zero cols)
            if ((oc | 31) >= i) {
                for (int k = 0; k < NHID; k += 4) {
                    float w0 = w2s[(k + 0) * D + oc], w1 = w2s[(k + 1) * D + oc];
                    float w2v = w2s[(k + 2) * D + oc], w3 = w2s[(k + 3) * D + oc];
                    #pragma unroll
                    for (int rr = 0; rr < 8; rr++) {
                        float4 tv = *(const float4*)(ts + (rbase + rr) * NHID + k);
                        yacc[rr] += tv.x * w0 + tv.y * w1 + tv.z * w2v + tv.w * w3;
                    }
                }
            }
            __syncthreads();
        }

        // ---- gate-combine and reverse (or final output)
        if (f < NF - 1) {
            float xo[8];
            #pragma unroll
            for (int rr = 0; rr < 8; rr++) {
                float xv = xs[(rbase + rr) * D + oc];
                xo[rr] = sg * yacc[rr] + (1.f - sg) * xv;
            }
            __syncthreads();
            #pragma unroll
            for (int rr = 0; rr < 8; rr++)
                xs[(rbase + rr) * D + (D - 1 - oc)] = xo[rr];
            __syncthreads();
        } else {
            #pragma unroll
            for (int rr = 0; rr < 8; rr++)
                out[(size_t)(b0 + rbase + rr) * D + oc] = yacc[rr];
        }
    }

    if (tid < BM) out[(size_t)BATCH * D + b0 + tid] = lds_s[tid];
}

static const int SMEM_BYTES = (BM * D + D * NHID + NHID * D + 2 * BM * NHID + BM) * 4;

extern "C" void kernel_launch(void* const* d_in, const int* in_sizes, int n_in,
                              void* d_out, int out_size) {
    const float* x  = (const float*)d_in[0];
    const float* W1 = (const float*)d_in[1];
    const float* d1 = (const float*)d_in[2];
    const float* b1 = (const float*)d_in[3];
    const float* W2 = (const float*)d_in[4];
    const float* d2 = (const float*)d_in[5];
    const float* b2 = (const float*)d_in[6];
    const float* gates = (const float*)d_in[7];
    float* out = (float*)d_out;

    prep1<<<(NF * H + 255) / 256, 256>>>(W1, d1);
    prep2<<<NF * D, 128>>>(W2, d2);

    cudaFuncSetAttribute(bnaf_main, cudaFuncAttributeMaxDynamicSharedMemorySize, SMEM_BYTES);
    bnaf_main<<<BATCH / BM, NTH, SMEM_BYTES>>>(x, b1, b2, gates, out);
}

// round 7
// speedup vs baseline: 1.2319x; 1.2318x over previous
#include <cuda_runtime.h>
#include <math.h>

#define NF 5
#define D 64
#define NHID 128
#define H 8192     /* D*NHID */
#define BATCH 4096
#define BM 32
#define NTH 512

#define XP   68    /* xs pitch   */
#define W1P  68    /* w1t pitch  */
#define W2P  132   /* w2t pitch  */
#define TSP  132   /* ts/ps pitch*/

// Precomputed normalized weights (batch-independent)
// g_wn1: [f][i][k][j]  (k=0..127 hidden-in-block, j=0..63; zeros stored for j>i)
__device__ float g_wn1[NF * D * NHID * D];
// g_wn2: [f][i][oc][k] (i = input hidden block, oc = output col, k in-block; zeros for oc<i)
__device__ float g_wn2[NF * D * D * NHID];
__device__ float g_c[NF * D * NHID];          // [f][i][k] = wpl1_diag + wpl2_diag

__device__ __forceinline__ float softplusf(float z) {
    return fmaxf(z, 0.f) + log1pf(expf(-fabsf(z)));
}

// ---------------------------------------------------------------------------
// prep1: row r=(i,k) of W1. w[j]=W1[r,j] (j<i), exp(W1[r,i]) (j==i), 0 (j>i).
// Normalize, scale by exp(d1). Store [f][i][k][j]. Also c = wpl1 diag.
// ---------------------------------------------------------------------------
__global__ void prep1(const float* __restrict__ W1, const float* __restrict__ d1) {
    int idx = blockIdx.x * blockDim.x + threadIdx.x;
    if (idx >= NF * H) return;
    int f = idx / H, r = idx % H;
    int i = r >> 7, k = r & 127;
    const float* Wrow = W1 + (size_t)(f * H + r) * D;
    float dv = d1[f * H + r];
    float wdiag = expf(Wrow[i]);
    float wsn = wdiag * wdiag;
    for (int j = 0; j < i; j++) { float wv = Wrow[j]; wsn += wv * wv; }
    float scale = expf(dv) * rsqrtf(wsn);
    float* dst = g_wn1 + ((size_t)(f * D + i) * NHID + k) * D;
    for (int j = 0; j < D; j++) {
        float wv = (j < i) ? Wrow[j] : ((j == i) ? wdiag : 0.f);
        dst[j] = wv * scale;
    }
    g_c[(f * D + i) * NHID + k] = dv + Wrow[i] - 0.5f * logf(wsn);
}

// ---------------------------------------------------------------------------
// prep2: one CTA per (flow, output col oc). Normalize row oc of W2, store
// as [f][jb][oc][k]. Adds wpl2 diag into g_c (ordered after prep1).
// ---------------------------------------------------------------------------
__global__ void prep2(const float* __restrict__ W2, const float* __restrict__ d2) {
    int f = blockIdx.x >> 6;
    int oc = blockIdx.x & 63;
    int tid = threadIdx.x;
    const float* Wrow = W2 + (size_t)(f * D + oc) * H;
    __shared__ float red[128];
    float wsn = 0.f;
    int lim = (oc + 1) * NHID;
    for (int j = tid; j < lim; j += 128) {
        int jb = j >> 7;
        float wv = (jb == oc) ? expf(Wrow[j]) : Wrow[j];
        wsn += wv * wv;
    }
    red[tid] = wsn;
    __syncthreads();
    for (int s = 64; s > 0; s >>= 1) {
        if (tid < s) red[tid] += red[tid + s];
        __syncthreads();
    }
    wsn = red[0];
    float dv = d2[f * D + oc];
    float scale = expf(dv) * rsqrtf(wsn);
    for (int j = tid; j < H; j += 128) {
        int jb = j >> 7, k = j & 127;
        float wv = (jb < oc) ? Wrow[j] : ((jb == oc) ? expf(Wrow[j]) : 0.f);
        g_wn2[((size_t)(f * D + jb) * D + oc) * NHID + k] = wv * scale;
    }
    g_c[(f * D + oc) * NHID + tid] += dv + Wrow[oc * NHID + tid] - 0.5f * logf(wsn);
}

// ---------------------------------------------------------------------------
// Main fused kernel. 128 CTAs x 512 threads (16 warps, 4/SMSP).
// Phase1: thread = (kc, 4 rows). Phase2: warp = 32 rows(lanes) x 4 uniform oc.
// ---------------------------------------------------------------------------
__global__ void __launch_bounds__(NTH, 1) bnaf_main(
    const float* __restrict__ x, const float* __restrict__ b1,
    const float* __restrict__ b2, const float* __restrict__ gates,
    float* __restrict__ out)
{
    extern __shared__ float sm[];
    float* xs  = sm;                     // BM*XP   = 2176
    float* w1t = xs + BM * XP;           // 128*W1P = 8704
    float* w2t = w1t + NHID * W1P;       // 64*W2P  = 8448
    float* ts  = w2t + D * W2P;          // BM*TSP  = 4224
    float* ps  = ts + BM * TSP;          // BM*TSP  = 4224
    float* lds_s = ps + BM * TSP;        // BM

    const int tid = threadIdx.x;
    const int b0 = blockIdx.x * BM;
    const float LN2 = 0.6931471805599453f;

    // phase1 mapping: kc (h column, +64 pair), 4 rows
    const int kc = tid & 63;
    const int rb = (tid >> 6) * 4;
    // phase2 mapping: warp -> 4 output cols (SMSP-balanced permutation), lane -> row
    const int wid = tid >> 5, lane = tid & 31;
    const int s_ = wid & 3, t_ = wid >> 2;
    const int gperm = ((t_ & 1) ? (7 - s_) : s_) + 8 * (t_ >> 1);
    const int oc0 = gperm * 4;
    // logsumexp mapping: 16 lanes per row
    const int lrow = tid >> 4, lsub = tid & 15;

    {   // load x tile, one float4 per thread, padded pitch
        int r = tid >> 4, c4 = tid & 15;
        *(float4*)(xs + r * XP + c4 * 4) =
            *(const float4*)(x + (size_t)(b0 + r) * D + c4 * 4);
    }
    if (tid < BM) lds_s[tid] = 0.f;
    __syncthreads();

    for (int f = 0; f < NF; f++) {
        const bool gated = (f < NF - 1);
        const float gate = gated ? gates[f] : 0.f;
        const float sg = gated ? (1.f / (1.f + expf(-gate))) : 0.f;
        const float spg = gated ? softplusf(gate) : 0.f;

        float yacc[4];
        #pragma unroll
        for (int u = 0; u < 4; u++) yacc[u] = b2[f * D + oc0 + u];

        const float* wn1f = g_wn1 + (size_t)f * D * NHID * D;
        const float* wn2f = g_wn2 + (size_t)f * D * D * NHID;

        for (int i = 0; i < D; i++) {
            const int jlim4 = (i >> 2) + 1;
            // ---- stage w1 (triangular, float4) and w2 tile (float4)
            {
                const float* w1src = wn1f + (size_t)i * NHID * D;
                #pragma unroll
                for (int q = tid; q < NHID * 16; q += NTH) {
                    int k = q >> 4, c4 = q & 15;
                    if (c4 < jlim4)
                        *(float4*)(w1t + k * W1P + c4 * 4) =
                            *(const float4*)(w1src + k * D + c4 * 4);
                }
                const float* w2src = wn2f + (size_t)i * D * NHID;
                #pragma unroll
                for (int q = tid; q < D * 32; q += NTH) {
                    int o = q >> 5, c4 = q & 31;
                    *(float4*)(w2t + o * W2P + c4 * 4) =
                        *(const float4*)(w2src + o * NHID + c4 * 4);
                }
            }
            __syncthreads();

            // ---- phase 1: h[r][kc], h[r][kc+64] for 4 rows, j<=i (zero tail staged)
            float a0[4], a1[4];
            {
                float b1a = b1[f * H + i * NHID + kc];
                float b1b = b1[f * H + i * NHID + kc + 64];
                #pragma unroll
                for (int rr = 0; rr < 4; rr++) { a0[rr] = b1a; a1[rr] = b1b; }
            }
            {
                const float* wa = w1t + kc * W1P;
                const float* wb = w1t + (kc + 64) * W1P;
                for (int j = 0; j <= i; j += 4) {
                    float4 w0 = *(const float4*)(wa + j);
                    float4 w1v = *(const float4*)(wb + j);
                    #pragma unroll
                    for (int rr = 0; rr < 4; rr++) {
                        float4 xv = *(const float4*)(xs + (rb + rr) * XP + j);
                        a0[rr] += xv.x * w0.x + xv.y * w0.y + xv.z * w0.z + xv.w * w0.w;
                        a1[rr] += xv.x * w1v.x + xv.y * w1v.y + xv.z * w1v.z + xv.w * w1v.w;
                    }
                }
            }

            // ---- tanh + stable log(1-tanh^2), write t and p tiles
            {
                float ca = g_c[(f * D + i) * NHID + kc];
                float cb = g_c[(f * D + i) * NHID + kc + 64];
                #pragma unroll
                for (int rr = 0; rr < 4; rr++) {
                    int r = rb + rr;
                    float h0 = a0[rr], h1 = a1[rr];
                    ts[r * TSP + kc]      = tanhf(h0);
                    ts[r * TSP + kc + 64] = tanhf(h1);
                    float l0 = -2.f * (h0 - LN2 + softplusf(-2.f * h0));
                    float l1 = -2.f * (h1 - LN2 + softplusf(-2.f * h1));
                    ps[r * TSP + kc]      = ca + l0;
                    ps[r * TSP + kc + 64] = cb + l1;
                }
            }
            __syncthreads();

            // ---- per-row logsumexp over 128 (16 lanes/row)
            {
                const float* pr = ps + lrow * TSP;
                float mx = -1e30f;
                #pragma unroll
                for (int m = 0; m < 8; m++) mx = fmaxf(mx, pr[lsub + 16 * m]);
                #pragma unroll
                for (int o = 8; o > 0; o >>= 1)
                    mx = fmaxf(mx, __shfl_xor_sync(0xffffffffu, mx, o));
                float se = 0.f;
                #pragma unroll
                for (int m = 0; m < 8; m++) se += expf(pr[lsub + 16 * m] - mx);
                #pragma unroll
                for (int o = 8; o > 0; o >>= 1)
                    se += __shfl_xor_sync(0xffffffffu, se, o);
                if (lsub == 0) {
                    float g = mx + logf(se);
                    lds_s[lrow] += gated ? (softplusf(g + gate) - spg) : g;
                }
            }

            // ---- phase 2: warp-uniform oc, exact triangular skip (oc>=i nonzero)
            if (oc0 + 3 >= i) {
                const float* tr  = ts + lane * TSP;
                const float* wv0 = w2t + (oc0 + 0) * W2P;
                const float* wv1 = w2t + (oc0 + 1) * W2P;
                const float* wv2 = w2t + (oc0 + 2) * W2P;
                const float* wv3 = w2t + (oc0 + 3) * W2P;
                for (int k = 0; k < NHID; k += 4) {
                    float4 tv = *(const float4*)(tr + k);
                    float4 u0 = *(const float4*)(wv0 + k);
                    float4 u1 = *(const float4*)(wv1 + k);
                    float4 u2 = *(const float4*)(wv2 + k);
                    float4 u3 = *(const float4*)(wv3 + k);
                    yacc[0] += tv.x * u0.x + tv.y * u0.y + tv.z * u0.z + tv.w * u0.w;
                    yacc[1] += tv.x * u1.x + tv.y * u1.y + tv.z * u1.z + tv.w * u1.w;
                    yacc[2] += tv.x * u2.x + tv.y * u2.y + tv.z * u2.z + tv.w * u2.w;
                    yacc[3] += tv.x * u3.x + tv.y * u3.y + tv.z * u3.z + tv.w * u3.w;
                }
            }
            __syncthreads();
        }

        // ---- gate-combine + reverse (or final output)
        if (gated) {
            float xo[4];
            #pragma unroll
            for (int u = 0; u < 4; u++) {
                float xv = xs[lane * XP + oc0 + u];
                xo[u] = sg * yacc[u] + (1.f - sg) * xv;
            }
            __syncthreads();
            #pragma unroll
            for (int u = 0; u < 4; u++)
                xs[lane * XP + (D - 1 - (oc0 + u))] = xo[u];
            __syncthreads();
        } else {
            #pragma unroll
            for (int u = 0; u < 4; u++)
                ps[lane * XP + oc0 + u] = yacc[u];
            __syncthreads();
            int r = tid >> 4, c4 = tid & 15;
            *(float4*)(out + (size_t)(b0 + r) * D + c4 * 4) =
                *(const float4*)(ps + r * XP + c4 * 4);
        }
    }

    if (tid < BM) out[(size_t)BATCH * D + b0 + tid] = lds_s[tid];
}

static const int SMEM_BYTES =
    (BM * XP + NHID * W1P + D * W2P + 2 * BM * TSP + BM) * 4;

extern "C" void kernel_launch(void* const* d_in, const int* in_sizes, int n_in,
                              void* d_out, int out_size) {
    const float* x  = (const float*)d_in[0];
    const float* W1 = (const float*)d_in[1];
    const float* d1 = (const float*)d_in[2];
    const float* b1 = (const float*)d_in[3];
    const float* W2 = (const float*)d_in[4];
    const float* d2 = (const float*)d_in[5];
    const float* b2 = (const float*)d_in[6];
    const float* gates = (const float*)d_in[7];
    float* out = (float*)d_out;

    prep1<<<(NF * H + 255) / 256, 256>>>(W1, d1);
    prep2<<<NF * D, 128>>>(W2, d2);

    cudaFuncSetAttribute(bnaf_main, cudaFuncAttributeMaxDynamicSharedMemorySize, SMEM_BYTES);
    bnaf_main<<<BATCH / BM, NTH, SMEM_BYTES>>>(x, b1, b2, gates, out);
}

// round 8
// speedup vs baseline: 1.4578x; 1.1834x over previous
#include <cuda_runtime.h>
#include <math.h>

#define NF 5
#define D 64
#define NHID 128
#define H 8192     /* D*NHID */
#define BATCH 4096
#define BM 32
#define NTH 512

#define XP   68    /* xs pitch   */
#define W1P  68    /* w1t pitch  */
#define W2P  132   /* w2t pitch  */
#define TSP  132   /* ts/ps pitch*/

// Precomputed normalized weights (batch-independent)
__device__ float g_wn1[NF * D * NHID * D];   // [f][i][k][j] (zeros for j>i)
__device__ float g_wn2[NF * D * D * NHID];   // [f][i][oc][k] (zeros for oc<i)
__device__ float g_c[NF * D * NHID];         // [f][i][k] = wpl1_diag + wpl2_diag

__device__ __forceinline__ float softplusf(float z) {
    return fmaxf(z, 0.f) + log1pf(expf(-fabsf(z)));
}
__device__ __forceinline__ float fast_sp(float z) {
    return fmaxf(z, 0.f) + __logf(1.f + __expf(-fabsf(z)));
}

// ---------------------------------------------------------------------------
__global__ void prep1(const float* __restrict__ W1, const float* __restrict__ d1) {
    int idx = blockIdx.x * blockDim.x + threadIdx.x;
    if (idx >= NF * H) return;
    int f = idx / H, r = idx % H;
    int i = r >> 7, k = r & 127;
    const float* Wrow = W1 + (size_t)(f * H + r) * D;
    float dv = d1[f * H + r];
    float wdiag = expf(Wrow[i]);
    float wsn = wdiag * wdiag;
    for (int j = 0; j < i; j++) { float wv = Wrow[j]; wsn += wv * wv; }
    float scale = expf(dv) * rsqrtf(wsn);
    float* dst = g_wn1 + ((size_t)(f * D + i) * NHID + k) * D;
    for (int j = 0; j < D; j++) {
        float wv = (j < i) ? Wrow[j] : ((j == i) ? wdiag : 0.f);
        dst[j] = wv * scale;
    }
    g_c[(f * D + i) * NHID + k] = dv + Wrow[i] - 0.5f * logf(wsn);
}

// ---------------------------------------------------------------------------
__global__ void prep2(const float* __restrict__ W2, const float* __restrict__ d2) {
    int f = blockIdx.x >> 6;
    int oc = blockIdx.x & 63;
    int tid = threadIdx.x;
    const float* Wrow = W2 + (size_t)(f * D + oc) * H;
    __shared__ float red[128];
    float wsn = 0.f;
    int lim = (oc + 1) * NHID;
    for (int j = tid; j < lim; j += 128) {
        int jb = j >> 7;
        float wv = (jb == oc) ? expf(Wrow[j]) : Wrow[j];
        wsn += wv * wv;
    }
    red[tid] = wsn;
    __syncthreads();
    for (int s = 64; s > 0; s >>= 1) {
        if (tid < s) red[tid] += red[tid + s];
        __syncthreads();
    }
    wsn = red[0];
    float dv = d2[f * D + oc];
    float scale = expf(dv) * rsqrtf(wsn);
    for (int j = tid; j < H; j += 128) {
        int jb = j >> 7, k = j & 127;
        float wv = (jb < oc) ? Wrow[j] : ((jb == oc) ? expf(Wrow[j]) : 0.f);
        g_wn2[((size_t)(f * D + jb) * D + oc) * NHID + k] = wv * scale;
    }
    g_c[(f * D + oc) * NHID + tid] += dv + Wrow[oc * NHID + tid] - 0.5f * logf(wsn);
}

// ---------------------------------------------------------------------------
// Main fused kernel. 128 CTAs x 512 threads. Double-buffered weight tiles,
// 2 barriers per i-iter, fast transcendentals, triangular staging/skip.
// ---------------------------------------------------------------------------
__global__ void __launch_bounds__(NTH, 1) bnaf_main(
    const float* __restrict__ x, const float* __restrict__ b1,
    const float* __restrict__ b2, const float* __restrict__ gates,
    float* __restrict__ out)
{
    extern __shared__ float sm[];
    float* xs  = sm;                         // BM*XP        = 2176
    float* w1t = xs + BM * XP;               // 2*128*W1P    = 17408
    float* w2t = w1t + 2 * NHID * W1P;       // 2*64*W2P     = 16896
    float* ts  = w2t + 2 * D * W2P;          // BM*TSP       = 4224
    float* ps  = ts + BM * TSP;              // BM*TSP       = 4224
    float* lds_s = ps + BM * TSP;            // BM

    const int tid = threadIdx.x;
    const int b0 = blockIdx.x * BM;
    const float LN2 = 0.6931471805599453f;

    // phase1 mapping: kc (h column, +64 pair), 4 rows
    const int kc = tid & 63;
    const int rb = (tid >> 6) * 4;
    // phase2 mapping: warp -> 4 output cols (SMSP-balanced), lane -> row
    const int wid = tid >> 5, lane = tid & 31;
    const int s_ = wid & 3, t_ = wid >> 2;
    const int gperm = ((t_ & 1) ? (7 - s_) : s_) + 8 * (t_ >> 1);
    const int oc0 = gperm * 4;
    // logsumexp mapping: 16 lanes per row
    const int lrow = tid >> 4, lsub = tid & 15;

    {   // load x tile
        int r = tid >> 4, c4 = tid & 15;
        *(float4*)(xs + r * XP + c4 * 4) =
            *(const float4*)(x + (size_t)(b0 + r) * D + c4 * 4);
    }
    if (tid < BM) lds_s[tid] = 0.f;

    // ---- prologue: stage tile for g=0 into buffer 0
    {
        const float* w1src = g_wn1;          // f=0,i=0
        for (int q = tid; q < NHID * 16; q += NTH) {
            int k = q >> 4, c4 = q & 15;
            if (c4 < 1)
                *(float4*)(w1t + k * W1P + c4 * 4) =
                    *(const float4*)(w1src + k * D + c4 * 4);
        }
        const float* w2src = g_wn2;
        for (int q = tid; q < D * 32; q += NTH) {
            int o = q >> 5, c4 = q & 31;
            *(float4*)(w2t + o * W2P + c4 * 4) =
                *(const float4*)(w2src + o * NHID + c4 * 4);
        }
    }
    __syncthreads();

    for (int f = 0; f < NF; f++) {
        const bool gated = (f < NF - 1);
        const float gate = gated ? gates[f] : 0.f;
        const float sg = gated ? (1.f / (1.f + __expf(-gate))) : 0.f;
        const float spg = gated ? fast_sp(gate) : 0.f;

        float yacc[4];
        #pragma unroll
        for (int u = 0; u < 4; u++) yacc[u] = b2[f * D + oc0 + u];

        for (int i = 0; i < D; i++) {
            const int g = f * D + i;
            const int buf = g & 1;
            const float* w1b = w1t + buf * (NHID * W1P);
            const float* w2b = w2t + buf * (D * W2P);

            // ---- phase 1: h[r][kc], h[r][kc+64] for 4 rows, j<=i
            float a0[4], a1[4];
            {
                float b1a = b1[f * H + i * NHID + kc];
                float b1b = b1[f * H + i * NHID + kc + 64];
                #pragma unroll
                for (int rr = 0; rr < 4; rr++) { a0[rr] = b1a; a1[rr] = b1b; }
            }
            {
                const float* wa = w1b + kc * W1P;
                const float* wb = w1b + (kc + 64) * W1P;
                #pragma unroll 4
                for (int j = 0; j <= i; j += 4) {
                    float4 w0 = *(const float4*)(wa + j);
                    float4 w1v = *(const float4*)(wb + j);
                    #pragma unroll
                    for (int rr = 0; rr < 4; rr++) {
                        float4 xv = *(const float4*)(xs + (rb + rr) * XP + j);
                        a0[rr] += xv.x * w0.x + xv.y * w0.y + xv.z * w0.z + xv.w * w0.w;
                        a1[rr] += xv.x * w1v.x + xv.y * w1v.y + xv.z * w1v.z + xv.w * w1v.w;
                    }
                }
            }

            // ---- fast tanh + log(1-tanh^2): E=e^{-2|h|}, shared by both
            {
                float ca = g_c[g * NHID + kc];
                float cb = g_c[g * NHID + kc + 64];
                #pragma unroll
                for (int rr = 0; rr < 4; rr++) {
                    int r = rb + rr;
                    float h0 = a0[rr], h1 = a1[rr];
                    float ah0 = fabsf(h0), ah1 = fabsf(h1);
                    float E0 = __expf(-2.f * ah0);
                    float E1 = __expf(-2.f * ah1);
                    float t0 = copysignf(__fdividef(1.f - E0, 1.f + E0), h0);
                    float t1 = copysignf(__fdividef(1.f - E1, 1.f + E1), h1);
                    ts[r * TSP + kc]      = t0;
                    ts[r * TSP + kc + 64] = t1;
                    float l0 = 2.f * (LN2 - ah0 - __logf(1.f + E0));
                    float l1 = 2.f * (LN2 - ah1 - __logf(1.f + E1));
                    ps[r * TSP + kc]      = ca + l0;
                    ps[r * TSP + kc + 64] = cb + l1;
                }
            }

            // ---- stage next tile into the other buffer (overlaps with above)
            if (g + 1 < NF * D) {
                int gn = g + 1;
                int in = gn & 63;
                int jl4 = (in >> 2) + 1;
                const float* w1src = g_wn1 + (size_t)gn * NHID * D;
                float* w1d = w1t + (buf ^ 1) * (NHID * W1P);
                #pragma unroll
                for (int q = tid; q < NHID * 16; q += NTH) {
                    int k = q >> 4, c4 = q & 15;
                    if (c4 < jl4)
                        *(float4*)(w1d + k * W1P + c4 * 4) =
                            *(const float4*)(w1src + k * D + c4 * 4);
                }
                const float* w2src = g_wn2 + (size_t)gn * D * NHID;
                float* w2d = w2t + (buf ^ 1) * (D * W2P);
                #pragma unroll
                for (int q = tid; q < D * 32; q += NTH) {
                    int o = q >> 5, c4 = q & 31;
                    if ((o | 3) >= in)
                        *(float4*)(w2d + o * W2P + c4 * 4) =
                            *(const float4*)(w2src + o * NHID + c4 * 4);
                }
            }
            __syncthreads();

            // ---- per-row logsumexp over 128 (16 lanes/row)
            {
                const float* pr = ps + lrow * TSP;
                float mx = -1e30f;
                #pragma unroll
                for (int m = 0; m < 8; m++) mx = fmaxf(mx, pr[lsub + 16 * m]);
                #pragma unroll
                for (int o = 8; o > 0; o >>= 1)
                    mx = fmaxf(mx, __shfl_xor_sync(0xffffffffu, mx, o));
                float se = 0.f;
                #pragma unroll
                for (int m = 0; m < 8; m++) se += __expf(pr[lsub + 16 * m] - mx);
                #pragma unroll
                for (int o = 8; o > 0; o >>= 1)
                    se += __shfl_xor_sync(0xffffffffu, se, o);
                if (lsub == 0) {
                    float gg = mx + __logf(se);
                    lds_s[lrow] += gated ? (fast_sp(gg + gate) - spg) : gg;
                }
            }

            // ---- phase 2: warp-uniform oc, exact triangular skip
            if (oc0 + 3 >= i) {
                const float* tr  = ts + lane * TSP;
                const float* wv0 = w2b + (oc0 + 0) * W2P;
                const float* wv1 = w2b + (oc0 + 1) * W2P;
                const float* wv2 = w2b + (oc0 + 2) * W2P;
                const float* wv3 = w2b + (oc0 + 3) * W2P;
                #pragma unroll 8
                for (int k = 0; k < NHID; k += 4) {
                    float4 tv = *(const float4*)(tr + k);
                    float4 u0 = *(const float4*)(wv0 + k);
                    float4 u1 = *(const float4*)(wv1 + k);
                    float4 u2 = *(const float4*)(wv2 + k);
                    float4 u3 = *(const float4*)(wv3 + k);
                    yacc[0] += tv.x * u0.x + tv.y * u0.y + tv.z * u0.z + tv.w * u0.w;
                    yacc[1] += tv.x * u1.x + tv.y * u1.y + tv.z * u1.z + tv.w * u1.w;
                    yacc[2] += tv.x * u2.x + tv.y * u2.y + tv.z * u2.z + tv.w * u2.w;
                    yacc[3] += tv.x * u3.x + tv.y * u3.y + tv.z * u3.z + tv.w * u3.w;
                }
            }
            __syncthreads();
        }

        // ---- gate-combine + reverse (or final output)
        if (gated) {
            float xo[4];
            #pragma unroll
            for (int u = 0; u < 4; u++) {
                float xv = xs[lane * XP + oc0 + u];
                xo[u] = sg * yacc[u] + (1.f - sg) * xv;
            }
            __syncthreads();
            #pragma unroll
            for (int u = 0; u < 4; u++)
                xs[lane * XP + (D - 1 - (oc0 + u))] = xo[u];
            __syncthreads();
        } else {
            #pragma unroll
            for (int u = 0; u < 4; u++)
                ps[lane * XP + oc0 + u] = yacc[u];
            __syncthreads();
            int r = tid >> 4, c4 = tid & 15;
            *(float4*)(out + (size_t)(b0 + r) * D + c4 * 4) =
                *(const float4*)(ps + r * XP + c4 * 4);
        }
    }

    if (tid < BM) out[(size_t)BATCH * D + b0 + tid] = lds_s[tid];
}

static const int SMEM_BYTES =
    (BM * XP + 2 * NHID * W1P + 2 * D * W2P + 2 * BM * TSP + BM) * 4;

extern "C" void kernel_launch(void* const* d_in, const int* in_sizes, int n_in,
                              void* d_out, int out_size) {
    const float* x  = (const float*)d_in[0];
    const float* W1 = (const float*)d_in[1];
    const float* d1 = (const float*)d_in[2];
    const float* b1 = (const float*)d_in[3];
    const float* W2 = (const float*)d_in[4];
    const float* d2 = (const float*)d_in[5];
    const float* b2 = (const float*)d_in[6];
    const float* gates = (const float*)d_in[7];
    float* out = (float*)d_out;

    prep1<<<(NF * H + 255) / 256, 256>>>(W1, d1);
    prep2<<<NF * D, 128>>>(W2, d2);

    cudaFuncSetAttribute(bnaf_main, cudaFuncAttributeMaxDynamicSharedMemorySize, SMEM_BYTES);
    bnaf_main<<<BATCH / BM, NTH, SMEM_BYTES>>>(x, b1, b2, gates, out);
}